// round 2
// baseline (speedup 1.0000x reference)
#include <cuda_runtime.h>

// image [8,512,512,16] f32, flow [8,512,512,2] f32, output [8,512,512,16] f32.
constexpr int B = 8;
constexpr int H = 512;
constexpr int W = 512;
constexpr int C = 16;               // floats per pixel
constexpr int C4 = C / 4;           // float4 chunks per pixel = 4
constexpr int NPIX = B * H * W;     // 2,097,152
constexpr int N4 = NPIX * C4;       // 8,388,608 float4 outputs
constexpr int HALF = N4 / 2;        // two elements per thread, stride HALF

__device__ __forceinline__ float4 lerp4(float4 a, float4 b, float t) {
    float4 r;
    r.x = fmaf(t, b.x - a.x, a.x);
    r.y = fmaf(t, b.y - a.y, a.y);
    r.z = fmaf(t, b.z - a.z, a.z);
    r.w = fmaf(t, b.w - a.w, a.w);
    return r;
}

__global__ __launch_bounds__(256)
void dense_image_warp_kernel(const float4* __restrict__ img,   // [B*H*W*C4]
                             const float2* __restrict__ flow,  // [B*H*W] (dy,dx)
                             float4* __restrict__ out)         // [B*H*W*C4]
{
    int tid = blockIdx.x * blockDim.x + threadIdx.x;
    if (tid >= HALF) return;

    int e0 = tid;
    int e1 = tid + HALF;

    // --- address generation for both elements (independent) ---
    int base[2];
    float axv[2], ayv[2];

    #pragma unroll
    for (int s = 0; s < 2; s++) {
        int e = (s == 0) ? e0 : e1;
        int pix   = e >> 2;
        int chunk = e & 3;

        int x = pix & (W - 1);
        int y = (pix >> 9) & (H - 1);
        int b = pix >> 18;

        float2 f = __ldcs(&flow[pix]);   // read-once: streaming load
        float qy = (float)y - f.x;
        float qx = (float)x - f.y;

        float fy = fminf(fmaxf(floorf(qy), 0.0f), (float)(H - 2));
        float fx = fminf(fmaxf(floorf(qx), 0.0f), (float)(W - 2));
        ayv[s] = fminf(fmaxf(qy - fy, 0.0f), 1.0f);
        axv[s] = fminf(fmaxf(qx - fx, 0.0f), 1.0f);
        int iy = (int)fy;
        int ix = (int)fx;

        base[s] = ((b * H + iy) * W + ix) * C4 + chunk;
    }

    // --- 8 independent corner loads, batched for MLP ---
    float4 tl0 = __ldg(&img[base[0]]);
    float4 tr0 = __ldg(&img[base[0] + C4]);
    float4 bl0 = __ldg(&img[base[0] + W * C4]);
    float4 br0 = __ldg(&img[base[0] + W * C4 + C4]);
    float4 tl1 = __ldg(&img[base[1]]);
    float4 tr1 = __ldg(&img[base[1] + C4]);
    float4 bl1 = __ldg(&img[base[1] + W * C4]);
    float4 br1 = __ldg(&img[base[1] + W * C4 + C4]);

    // --- blend + streaming stores (write-once data, keep image in L2) ---
    float4 r0 = lerp4(lerp4(tl0, tr0, axv[0]), lerp4(bl0, br0, axv[0]), ayv[0]);
    float4 r1 = lerp4(lerp4(tl1, tr1, axv[1]), lerp4(bl1, br1, axv[1]), ayv[1]);

    __stcs(&out[e0], r0);
    __stcs(&out[e1], r1);
}

extern "C" void kernel_launch(void* const* d_in, const int* in_sizes, int n_in,
                              void* d_out, int out_size) {
    const float4* img  = (const float4*)d_in[0];
    const float2* flow = (const float2*)d_in[1];
    float4* out = (float4*)d_out;

    int threads = 256;
    int blocks = (HALF + threads - 1) / threads;
    dense_image_warp_kernel<<<blocks, threads>>>(img, flow, out);
}

// round 6
// speedup vs baseline: 1.0241x; 1.0241x over previous
#include <cuda_runtime.h>

// image [8,512,512,16] f32, flow [8,512,512,2] f32, output [8,512,512,16] f32.
constexpr int B = 8;
constexpr int H = 512;
constexpr int W = 512;
constexpr int C = 16;               // floats per pixel
constexpr int C4 = C / 4;           // float4 chunks per pixel = 4
constexpr int NPIX = B * H * W;     // 2,097,152
constexpr int N4 = NPIX * C4;       // 8,388,608 float4 outputs

__device__ __forceinline__ float4 lerp4(float4 a, float4 b, float t) {
    float4 r;
    r.x = fmaf(t, b.x - a.x, a.x);
    r.y = fmaf(t, b.y - a.y, a.y);
    r.z = fmaf(t, b.z - a.z, a.z);
    r.w = fmaf(t, b.w - a.w, a.w);
    return r;
}

__global__ __launch_bounds__(256)
void dense_image_warp_kernel(const float4* __restrict__ img,   // [B*H*W*C4]
                             const float2* __restrict__ flow,  // [B*H*W] (dy,dx)
                             float4* __restrict__ out)         // [B*H*W*C4]
{
    int tid = blockIdx.x * blockDim.x + threadIdx.x;
    if (tid >= N4) return;

    int pix   = tid >> 2;       // pixel index
    int chunk = tid & 3;        // which float4 of the 16 channels

    int x = pix & (W - 1);
    int y = (pix >> 9) & (H - 1);
    int b = pix >> 18;

    float2 f = __ldcs(&flow[pix]);   // read-once flow: evict-first
    float qy = (float)y - f.x;
    float qx = (float)x - f.y;

    // tfa clamping: floor clamped to [0, size-2], alpha clamped to [0,1]
    float fy = fminf(fmaxf(floorf(qy), 0.0f), (float)(H - 2));
    float fx = fminf(fmaxf(floorf(qx), 0.0f), (float)(W - 2));
    float ay = fminf(fmaxf(qy - fy, 0.0f), 1.0f);
    float ax = fminf(fmaxf(qx - fx, 0.0f), 1.0f);
    int iy = (int)fy;
    int ix = (int)fx;

    int base = ((b * H + iy) * W + ix) * C4 + chunk;

    float4 tl = __ldg(&img[base]);
    float4 tr = __ldg(&img[base + C4]);           // ix+1
    float4 bl = __ldg(&img[base + W * C4]);       // iy+1
    float4 br = __ldg(&img[base + W * C4 + C4]);  // iy+1, ix+1

    float4 top = lerp4(tl, tr, ax);
    float4 bot = lerp4(bl, br, ax);
    float4 res = lerp4(top, bot, ay);

    // Write-through streaming store: do NOT allocate output lines in L2,
    // so L2 retains the read-only image across graph replays.
    __stwt(&out[tid], res);
}

extern "C" void kernel_launch(void* const* d_in, const int* in_sizes, int n_in,
                              void* d_out, int out_size) {
    const float4* img  = (const float4*)d_in[0];
    const float2* flow = (const float2*)d_in[1];
    float4* out = (float4*)d_out;

    int threads = 256;
    int blocks = (N4 + threads - 1) / threads;
    dense_image_warp_kernel<<<blocks, threads>>>(img, flow, out);
}